// round 9
// baseline (speedup 1.0000x reference)
#include <cuda_runtime.h>
#include <math.h>

// Problem constants (fixed by the dataset)
#define TT      128
#define NCH     1536
#define NC0     10000
#define NCROSS  30000
#define NE      120000
#define DEGCAP  32            // P(Poisson(4) > 32) ~ 1e-22; safe fixed bucket
#define L2E     1.44269504088896f

// ---------------- scratch (static device allocations) ----------------
__device__ float4 g_nb[NCROSS];            // (sbase*, dbase*, qbase, -) [* log2e-scaled]
__device__ int    g_chanA[NCROSS];
__device__ int    g_chanB[NCROSS];
__device__ float4 g_s4[NCROSS * 32];       // [n][lane] = s ticks 4l..4l+3 (scaled)
__device__ float4 g_q4[NCROSS * 32];       // [n][lane] = q ticks 4l..4l+3
__device__ int    g_cnt[NCROSS];
__device__ int    g_csr[NCROSS * DEGCAP];  // entries pre-multiplied by 32
__device__ float  g_coef[12];              // sA sB sT dA dB dT qA qB qT bm (s,d scaled)

// ---------------- init ----------------
// W rows (13x4 row-major): 0 sigA, 1 wireA, 2 chanA, 3 zero, 4 planeA,
// 5 sigB, 6 wireB, 7 chanB, 8 zero, 9 planeB, 10 ray_x, 11 ray_y, 12 tick
__global__ void k_init(
    const int* __restrict__ c0, const int* __restrict__ c1, const int* __restrict__ c2,
    const int* __restrict__ g01, const int* __restrict__ g12, const int* __restrict__ g20,
    const float* __restrict__ r01, const float* __restrict__ r12, const float* __restrict__ r20,
    const float* __restrict__ W, const float* __restrict__ bg,
    const float* __restrict__ asrc, const float* __restrict__ adst,
    const float* __restrict__ Wm, const float* __restrict__ bm)
{
    int i = blockIdx.x * blockDim.x + threadIdx.x;
    if (i == 0) {
        float sA = 0, sB = 0, sT = 0, dA = 0, dB = 0, dT = 0, qA = 0, qB = 0, qT = 0;
#pragma unroll
        for (int o = 0; o < 4; o++) {
            float wA = W[o], wB = W[20 + o], wT = W[48 + o];
            sA += wA * asrc[o]; sB += wB * asrc[o]; sT += wT * asrc[o];
            dA += wA * adst[o]; dB += wB * adst[o]; dT += wT * adst[o];
            qA += wA * Wm[o];   qB += wB * Wm[o];   qT += wT * Wm[o];
        }
        g_coef[0] = sA * L2E; g_coef[1] = sB * L2E; g_coef[2] = sT * L2E;
        g_coef[3] = dA * L2E; g_coef[4] = dB * L2E; g_coef[5] = dT * L2E;
        g_coef[6] = qA; g_coef[7] = qB; g_coef[8] = qT;
        g_coef[9] = bm[0];
    }
    if (i >= NCROSS) return;
    g_cnt[i] = 0;

    int p = i / NC0, c = i % NC0;
    const int* g; const float* r; const int* cA; const int* cB; float pA, pB;
    if (p == 0)      { g = g01; r = r01; cA = c0; cB = c1; pA = 0.f; pB = 1.f; }
    else if (p == 1) { g = g12; r = r12; cA = c1; cB = c2; pA = 1.f; pB = 2.f; }
    else             { g = g20; r = r20; cA = c2; cB = c0; pA = 2.f; pB = 0.f; }
    int wA = g[2 * c], wB = g[2 * c + 1];
    int chA = cA[wA], chB = cB[wB];
    float rx = r[2 * c], ry = r[2 * c + 1];
    float fwA = (float)wA, fwB = (float)wB, fcA = (float)chA, fcB = (float)chB;
    float sb = 0.f, db = 0.f, qb = 0.f;
#pragma unroll
    for (int o = 0; o < 4; o++) {
        float base = bg[o]
              + fwA * W[4  + o] + fcA * W[8  + o] + pA * W[16 + o]
              + fwB * W[24 + o] + fcB * W[28 + o] + pB * W[36 + o]
              + rx  * W[40 + o] + ry  * W[44 + o];
        sb += base * asrc[o];
        db += base * adst[o];
        qb += base * Wm[o];
    }
    g_nb[i]    = make_float4(sb * L2E, db * L2E, qb, 0.f);
    g_chanA[i] = chA;
    g_chanB[i] = chB;
}

// ---------------- bucket scatter (4 edges/thread) ----------------
__global__ void k_scatter(const int* __restrict__ edges) {
    int q = blockIdx.x * blockDim.x + threadIdx.x;     // quad index
    if (q >= NE / 4) return;
    const int4* src4 = (const int4*)edges;
    const int4* dst4 = (const int4*)(edges + NE);
    int4 s = src4[q];
    int4 d = dst4[q];
    int p0 = atomicAdd(&g_cnt[d.x], 1);
    int p1 = atomicAdd(&g_cnt[d.y], 1);
    int p2 = atomicAdd(&g_cnt[d.z], 1);
    int p3 = atomicAdd(&g_cnt[d.w], 1);
    if (p0 < DEGCAP) g_csr[d.x * DEGCAP + p0] = s.x * 32;
    if (p1 < DEGCAP) g_csr[d.y * DEGCAP + p1] = s.y * 32;
    if (p2 < DEGCAP) g_csr[d.z * DEGCAP + p2] = s.z * 32;
    if (p3 < DEGCAP) g_csr[d.w * DEGCAP + p3] = s.w * 32;
}

// ---------------- s, q for all (n, t): thread owns 4 consecutive ticks ----------------
__global__ __launch_bounds__(256) void k_sdq(const float* __restrict__ x)
{
    int idx = blockIdx.x * blockDim.x + threadIdx.x;   // [0, NCROSS*32)
    if (idx >= NCROSS * 32) return;
    int n = idx >> 5;
    int l = idx & 31;
    const float4* x4 = (const float4*)x;
    float4 xA = __ldg(&x4[g_chanA[n] * 32 + l]);
    float4 xB = __ldg(&x4[g_chanB[n] * 32 + l]);
    float4 nb = g_nb[n];
    float cSA = g_coef[0], cSB = g_coef[1], cST = g_coef[2];
    float cQA = g_coef[6], cQB = g_coef[7], cQT = g_coef[8];
    float t0 = (float)(4 * l);
    float xa[4] = { xA.x, xA.y, xA.z, xA.w };
    float xb[4] = { xB.x, xB.y, xB.z, xB.w };
    float sv[4], qv[4];
#pragma unroll
    for (int k = 0; k < 4; k++) {
        float tk = t0 + (float)k;
        sv[k] = nb.x + xa[k] * cSA + xb[k] * cSB + tk * cST;
        qv[k] = nb.z + xa[k] * cQA + xb[k] * cQB + tk * cQT;
    }
    g_s4[idx] = make_float4(sv[0], sv[1], sv[2], sv[3]);
    g_q4[idx] = make_float4(qv[0], qv[1], qv[2], qv[3]);
}

// ---------------- GAT aggregation + MLP + sigmoid + transposed store ----------------
// Warp = node, lane = 4 consecutive ticks, 8 nodes/block.
// Pass A: running max of s ONLY (leaky/+d are monotone, so
//   max_j leaky(s_j + d) = leaky(max_j s_j + d) -- compute m once after).
// Pass B: w = exp2(max(u, 0.2u) - m), u = s + d.  den >= 1 guaranteed.
__global__ __launch_bounds__(256) void k_agg(const float* __restrict__ x,
                                             float* __restrict__ out)
{
    __shared__ float s_res[TT * 9];
    int tid  = threadIdx.x;
    int warp = tid >> 5, lane = tid & 31;
    int n0 = blockIdx.x * 8;
    int n  = n0 + warp;
    int deg = g_cnt[n];
    if (deg > DEGCAP) deg = DEGCAP;
    const int* row = g_csr + n * DEGCAP;
    float bmlp = g_coef[9];
    float cDA = g_coef[3], cDB = g_coef[4], cDT = g_coef[5];

    // dv for this lane's 4 ticks (scaled domain)
    const float4* x4 = (const float4*)x;
    float4 nb = g_nb[n];
    float4 xA = x4[g_chanA[n] * 32 + lane];
    float4 xB = x4[g_chanB[n] * 32 + lane];
    float t0f = (float)(4 * lane);
    float xa[4] = { xA.x, xA.y, xA.z, xA.w };
    float xb[4] = { xB.x, xB.y, xB.z, xB.w };
    float dv[4], sm[4];
#pragma unroll
    for (int k = 0; k < 4; k++) {
        dv[k] = nb.y + xa[k] * cDA + xb[k] * cDB + (t0f + (float)k) * cDT;
        sm[k] = -1e30f;
    }

    // ---- Pass A: max of s only (1 FMNMX per edge-tick) ----
    int rv_next = (deg > 0) ? row[0] : 0;
    for (int j = 0; j < deg; j++) {
        int rv = rv_next;
        if (j + 1 < deg) rv_next = row[j + 1];
        float4 sv = g_s4[rv + lane];
        sm[0] = fmaxf(sm[0], sv.x);
        sm[1] = fmaxf(sm[1], sv.y);
        sm[2] = fmaxf(sm[2], sv.z);
        sm[3] = fmaxf(sm[3], sv.w);
    }
    // m = leaky(smax + d) per tick
    float m[4], den[4], acc[4];
#pragma unroll
    for (int k = 0; k < 4; k++) {
        float u = sm[k] + dv[k];
        m[k] = fmaxf(u, 0.2f * u);
        den[k] = 0.f;
        acc[k] = 0.f;
    }

    // ---- Pass B: exp2 accumulate (data now L1-hot) ----
    rv_next = (deg > 0) ? row[0] : 0;
    for (int j = 0; j < deg; j++) {
        int rv = rv_next;
        if (j + 1 < deg) rv_next = row[j + 1];
        float4 sv = g_s4[rv + lane];
        float4 qv = g_q4[rv + lane];
        float ss[4] = { sv.x, sv.y, sv.z, sv.w };
        float qs[4] = { qv.x, qv.y, qv.z, qv.w };
#pragma unroll
        for (int k = 0; k < 4; k++) {
            float u = ss[k] + dv[k];                       // FADD
            float arg = fmaxf(u - m[k], fmaf(0.2f, u, -m[k]));  // FADD+FFMA+FMNMX
            float w = exp2f(arg);                          // MUFU
            den[k] += w;                                   // FADD
            acc[k] = fmaf(w, qs[k], acc[k]);               // FFMA
        }
    }

#pragma unroll
    for (int k = 0; k < 4; k++) {
        int t = 4 * lane + k;
        float z = acc[k] / (den[k] + 1e-9f) + bmlp;
        s_res[t * 9 + warp] = 1.f / (1.f + __expf(-z));
    }
    __syncthreads();
#pragma unroll
    for (int p = 0; p < 4; p++) {
        int i = p * 256 + tid;
        int t = i >> 3, c = i & 7;
        out[t * NCROSS + n0 + c] = s_res[t * 9 + c];
    }
}

// ---------------- launch ----------------
extern "C" void kernel_launch(void* const* d_in, const int* in_sizes, int n_in,
                              void* d_out, int out_size)
{
    const float* x    = (const float*)d_in[0];
    const int*   c0   = (const int*)  d_in[1];
    const int*   c1   = (const int*)  d_in[2];
    const int*   c2   = (const int*)  d_in[3];
    const int*   g01  = (const int*)  d_in[4];
    const int*   g12  = (const int*)  d_in[5];
    const int*   g20  = (const int*)  d_in[6];
    const float* r01  = (const float*)d_in[7];
    const float* r12  = (const float*)d_in[8];
    const float* r20  = (const float*)d_in[9];
    const int*   edges= (const int*)  d_in[10];
    const float* Wg   = (const float*)d_in[11];
    const float* asrc = (const float*)d_in[12];
    const float* adst = (const float*)d_in[13];
    const float* bg   = (const float*)d_in[14];
    const float* Wm   = (const float*)d_in[15];
    const float* bm   = (const float*)d_in[16];
    float* out = (float*)d_out;

    const int B = 256;
    k_init<<<(NCROSS + B - 1) / B, B>>>(c0, c1, c2, g01, g12, g20,
                                        r01, r12, r20, Wg, bg, asrc, adst, Wm, bm);
    k_scatter<<<(NE / 4 + B - 1) / B, B>>>(edges);
    k_sdq<<<(NCROSS * 32 + B - 1) / B, B>>>(x);
    k_agg<<<NCROSS / 8, B>>>(x, out);
}

// round 11
// speedup vs baseline: 1.0109x; 1.0109x over previous
#include <cuda_runtime.h>
#include <math.h>

// Problem constants (fixed by the dataset)
#define TT      128
#define TT2     64
#define NCH     1536
#define NC0     10000
#define NCROSS  30000
#define NE      120000
#define DEGCAP  32            // P(Poisson(4) > 32) ~ 1e-22; safe fixed bucket
#define L2E     1.44269504088896f

// ---------------- scratch (static device allocations) ----------------
__device__ float4 g_nb[NCROSS];            // (sbase*, dbase*, qbase, -) [* log2e-scaled]
__device__ int    g_chanA[NCROSS];
__device__ int    g_chanB[NCROSS];
__device__ float4 g_sq4[NCROSS * TT2];     // [n][tp] = (s0,q0,s1,q1), s scaled
__device__ int    g_cnt[NCROSS];
__device__ int    g_csr[NCROSS * DEGCAP];  // entries pre-multiplied by 64
__device__ float  g_coef[12];              // sA sB sT dA dB dT qA qB qT bm (s,d scaled)

// ---------------- init ----------------
// W rows (13x4 row-major): 0 sigA, 1 wireA, 2 chanA, 3 zero, 4 planeA,
// 5 sigB, 6 wireB, 7 chanB, 8 zero, 9 planeB, 10 ray_x, 11 ray_y, 12 tick
__global__ void k_init(
    const int* __restrict__ c0, const int* __restrict__ c1, const int* __restrict__ c2,
    const int* __restrict__ g01, const int* __restrict__ g12, const int* __restrict__ g20,
    const float* __restrict__ r01, const float* __restrict__ r12, const float* __restrict__ r20,
    const float* __restrict__ W, const float* __restrict__ bg,
    const float* __restrict__ asrc, const float* __restrict__ adst,
    const float* __restrict__ Wm, const float* __restrict__ bm)
{
    int i = blockIdx.x * blockDim.x + threadIdx.x;
    if (i == 0) {
        float sA = 0, sB = 0, sT = 0, dA = 0, dB = 0, dT = 0, qA = 0, qB = 0, qT = 0;
#pragma unroll
        for (int o = 0; o < 4; o++) {
            float wA = W[o], wB = W[20 + o], wT = W[48 + o];
            sA += wA * asrc[o]; sB += wB * asrc[o]; sT += wT * asrc[o];
            dA += wA * adst[o]; dB += wB * adst[o]; dT += wT * adst[o];
            qA += wA * Wm[o];   qB += wB * Wm[o];   qT += wT * Wm[o];
        }
        g_coef[0] = sA * L2E; g_coef[1] = sB * L2E; g_coef[2] = sT * L2E;
        g_coef[3] = dA * L2E; g_coef[4] = dB * L2E; g_coef[5] = dT * L2E;
        g_coef[6] = qA; g_coef[7] = qB; g_coef[8] = qT;
        g_coef[9] = bm[0];
    }
    if (i >= NCROSS) return;
    g_cnt[i] = 0;

    int p = i / NC0, c = i % NC0;
    const int* g; const float* r; const int* cA; const int* cB; float pA, pB;
    if (p == 0)      { g = g01; r = r01; cA = c0; cB = c1; pA = 0.f; pB = 1.f; }
    else if (p == 1) { g = g12; r = r12; cA = c1; cB = c2; pA = 1.f; pB = 2.f; }
    else             { g = g20; r = r20; cA = c2; cB = c0; pA = 2.f; pB = 0.f; }
    int wA = g[2 * c], wB = g[2 * c + 1];
    int chA = cA[wA], chB = cB[wB];
    float rx = r[2 * c], ry = r[2 * c + 1];
    float fwA = (float)wA, fwB = (float)wB, fcA = (float)chA, fcB = (float)chB;
    float sb = 0.f, db = 0.f, qb = 0.f;
#pragma unroll
    for (int o = 0; o < 4; o++) {
        float base = bg[o]
              + fwA * W[4  + o] + fcA * W[8  + o] + pA * W[16 + o]
              + fwB * W[24 + o] + fcB * W[28 + o] + pB * W[36 + o]
              + rx  * W[40 + o] + ry  * W[44 + o];
        sb += base * asrc[o];
        db += base * adst[o];
        qb += base * Wm[o];
    }
    g_nb[i]    = make_float4(sb * L2E, db * L2E, qb, 0.f);
    g_chanA[i] = chA;
    g_chanB[i] = chB;
}

// ---------------- bucket scatter (4 edges/thread) ----------------
__global__ void k_scatter(const int* __restrict__ edges) {
    int q = blockIdx.x * blockDim.x + threadIdx.x;
    if (q >= NE / 4) return;
    const int4* src4 = (const int4*)edges;
    const int4* dst4 = (const int4*)(edges + NE);
    int4 s = src4[q];
    int4 d = dst4[q];
    int p0 = atomicAdd(&g_cnt[d.x], 1);
    int p1 = atomicAdd(&g_cnt[d.y], 1);
    int p2 = atomicAdd(&g_cnt[d.z], 1);
    int p3 = atomicAdd(&g_cnt[d.w], 1);
    if (p0 < DEGCAP) g_csr[d.x * DEGCAP + p0] = s.x * TT2;
    if (p1 < DEGCAP) g_csr[d.y * DEGCAP + p1] = s.y * TT2;
    if (p2 < DEGCAP) g_csr[d.z * DEGCAP + p2] = s.z * TT2;
    if (p3 < DEGCAP) g_csr[d.w * DEGCAP + p3] = s.w * TT2;
}

// ---------------- s, q for all (n, t) [n-major, 2 ticks/thread] ----------------
__global__ __launch_bounds__(256) void k_sdq(const float* __restrict__ x)
{
    int idx = blockIdx.x * blockDim.x + threadIdx.x;   // [0, NCROSS*TT2)
    if (idx >= NCROSS * TT2) return;
    int n  = idx / TT2;
    int tp = idx % TT2;
    const float2* x2 = (const float2*)x;
    float2 xA = __ldg(&x2[g_chanA[n] * TT2 + tp]);
    float2 xB = __ldg(&x2[g_chanB[n] * TT2 + tp]);
    float4 nb = g_nb[n];
    float t0 = (float)(2 * tp), t1 = t0 + 1.f;
    float cSA = g_coef[0], cSB = g_coef[1], cST = g_coef[2];
    float cQA = g_coef[6], cQB = g_coef[7], cQT = g_coef[8];

    float s0 = nb.x + xA.x * cSA + xB.x * cSB + t0 * cST;
    float s1 = nb.x + xA.y * cSA + xB.y * cSB + t1 * cST;
    float q0 = nb.z + xA.x * cQA + xB.x * cQB + t0 * cQT;
    float q1 = nb.z + xA.y * cQA + xB.y * cQB + t1 * cQT;

    g_sq4[idx] = make_float4(s0, q0, s1, q1);
}

// ---------------- GAT aggregation (online softmax, 1 MUFU/edge-tick) ----------------
// Warp = node; lane owns ticks {2l, 2l+1, 64+2l, 65+2l}; 8 nodes/block.
// Online update with single exp: a = exp2(-|e-m|); (r,w) = e>m ? (a,1) : (1,a).
__global__ __launch_bounds__(256) void k_agg(const float* __restrict__ x,
                                             float* __restrict__ out)
{
    __shared__ float s_res[TT * 9];
    int tid  = threadIdx.x;
    int warp = tid >> 5, lane = tid & 31;
    int n0 = blockIdx.x * 8;
    int n  = n0 + warp;
    int deg = g_cnt[n];
    if (deg > DEGCAP) deg = DEGCAP;
    const int* row = g_csr + n * DEGCAP;
    float bmlp = g_coef[9];
    float cDA = g_coef[3], cDB = g_coef[4], cDT = g_coef[5];

    // dv for this lane's 4 ticks (scaled domain)
    const float2* x2 = (const float2*)x;
    float4 nb = g_nb[n];
    int chA = g_chanA[n], chB = g_chanB[n];
    float dv[4], m[4], den[4], acc[4];
#pragma unroll
    for (int k = 0; k < 2; k++) {
        float2 xA = x2[chA * TT2 + lane + 32 * k];
        float2 xB = x2[chB * TT2 + lane + 32 * k];
        float t0 = (float)(2 * (lane + 32 * k));
        dv[2 * k]     = nb.y + xA.x * cDA + xB.x * cDB + t0 * cDT;
        dv[2 * k + 1] = nb.y + xA.y * cDA + xB.y * cDB + (t0 + 1.f) * cDT;
    }
#pragma unroll
    for (int k = 0; k < 4; k++) { m[k] = -1e30f; den[k] = 0.f; acc[k] = 0.f; }

    int rv_next = (deg > 0) ? row[0] : 0;
    for (int j = 0; j < deg; j++) {
        int rv = rv_next;
        if (j + 1 < deg) rv_next = row[j + 1];
        float4 sq0 = g_sq4[rv + lane];        // ticks 2l, 2l+1
        float4 sq1 = g_sq4[rv + 32 + lane];   // ticks 64+2l, 65+2l
        float es[4] = { sq0.x, sq0.z, sq1.x, sq1.z };
        float qs[4] = { sq0.y, sq0.w, sq1.y, sq1.w };
#pragma unroll
        for (int k = 0; k < 4; k++) {
            float e = es[k] + dv[k];
            e = fmaxf(e, 0.2f * e);                 // leaky (scaled domain)
            float delta = e - m[k];
            float a = exp2f(-fabsf(delta));         // single MUFU
            bool gt = delta > 0.f;
            float r = gt ? a : 1.f;
            float w = gt ? 1.f : a;
            m[k] = fmaxf(m[k], e);
            den[k] = fmaf(den[k], r, w);
            acc[k] = fmaf(acc[k], r, w * qs[k]);
        }
    }
    // ticks for k: 0->2l, 1->2l+1, 2->64+2l, 3->65+2l
#pragma unroll
    for (int k = 0; k < 4; k++) {
        int t = 2 * lane + (k & 1) + 64 * (k >> 1);
        float z = acc[k] / (den[k] + 1e-9f) + bmlp;
        s_res[t * 9 + warp] = 1.f / (1.f + __expf(-z));
    }
    __syncthreads();
#pragma unroll
    for (int p = 0; p < 4; p++) {
        int i = p * 256 + tid;
        int t = i >> 3, c = i & 7;
        out[t * NCROSS + n0 + c] = s_res[t * 9 + c];
    }
}

// ---------------- launch ----------------
extern "C" void kernel_launch(void* const* d_in, const int* in_sizes, int n_in,
                              void* d_out, int out_size)
{
    const float* x    = (const float*)d_in[0];
    const int*   c0   = (const int*)  d_in[1];
    const int*   c1   = (const int*)  d_in[2];
    const int*   c2   = (const int*)  d_in[3];
    const int*   g01  = (const int*)  d_in[4];
    const int*   g12  = (const int*)  d_in[5];
    const int*   g20  = (const int*)  d_in[6];
    const float* r01  = (const float*)d_in[7];
    const float* r12  = (const float*)d_in[8];
    const float* r20  = (const float*)d_in[9];
    const int*   edges= (const int*)  d_in[10];
    const float* Wg   = (const float*)d_in[11];
    const float* asrc = (const float*)d_in[12];
    const float* adst = (const float*)d_in[13];
    const float* bg   = (const float*)d_in[14];
    const float* Wm   = (const float*)d_in[15];
    const float* bm   = (const float*)d_in[16];
    float* out = (float*)d_out;

    const int B = 256;
    k_init<<<(NCROSS + B - 1) / B, B>>>(c0, c1, c2, g01, g12, g20,
                                        r01, r12, r20, Wg, bg, asrc, adst, Wm, bm);
    k_scatter<<<(NE / 4 + B - 1) / B, B>>>(edges);
    k_sdq<<<(NCROSS * TT2 + B - 1) / B, B>>>(x);
    k_agg<<<NCROSS / 8, B>>>(x, out);
}

// round 12
// speedup vs baseline: 1.1812x; 1.1685x over previous
#include <cuda_runtime.h>
#include <math.h>

// Problem constants (fixed by the dataset)
#define TT      128
#define TT2     64
#define NCH     1536
#define NC0     10000
#define NCROSS  30000
#define NE      120000
#define DEGCAP  32            // P(Poisson(4) > 32) ~ 1e-22; safe fixed bucket
#define L2E     1.44269504088896f
#define SCATB   ((NE + 255) / 256)          // 469 scatter blocks (1 edge/thread)
#define SDQB    ((NCROSS * TT2 + 255) / 256) // 7500 sdq blocks

// ---------------- scratch (static device allocations) ----------------
__device__ float4 g_nb[NCROSS];            // (sbase*, dbase*, qbase, -) [* log2e-scaled]
__device__ int    g_chanA[NCROSS];
__device__ int    g_chanB[NCROSS];
__device__ float4 g_sq4[NCROSS * TT2];     // [n][tp] = (s0,q0,s1,q1), s scaled
__device__ int    g_cnt[NCROSS];
__device__ int    g_csr[NCROSS * DEGCAP];  // entries pre-multiplied by TT2
__device__ float  g_coef[12];              // sA sB sT dA dB dT qA qB qT bm (s,d scaled)

// ---------------- init: zero counts + coefficients + node statics ----------------
// W rows (13x4 row-major): 0 sigA, 1 wireA, 2 chanA, 3 zero, 4 planeA,
// 5 sigB, 6 wireB, 7 chanB, 8 zero, 9 planeB, 10 ray_x, 11 ray_y, 12 tick
__global__ void k_init(
    const int* __restrict__ c0, const int* __restrict__ c1, const int* __restrict__ c2,
    const int* __restrict__ g01, const int* __restrict__ g12, const int* __restrict__ g20,
    const float* __restrict__ r01, const float* __restrict__ r12, const float* __restrict__ r20,
    const float* __restrict__ W, const float* __restrict__ bg,
    const float* __restrict__ asrc, const float* __restrict__ adst,
    const float* __restrict__ Wm, const float* __restrict__ bm)
{
    int i = blockIdx.x * blockDim.x + threadIdx.x;
    if (i == 0) {
        float sA = 0, sB = 0, sT = 0, dA = 0, dB = 0, dT = 0, qA = 0, qB = 0, qT = 0;
#pragma unroll
        for (int o = 0; o < 4; o++) {
            float wA = W[o], wB = W[20 + o], wT = W[48 + o];
            sA += wA * asrc[o]; sB += wB * asrc[o]; sT += wT * asrc[o];
            dA += wA * adst[o]; dB += wB * adst[o]; dT += wT * adst[o];
            qA += wA * Wm[o];   qB += wB * Wm[o];   qT += wT * Wm[o];
        }
        g_coef[0] = sA * L2E; g_coef[1] = sB * L2E; g_coef[2] = sT * L2E;
        g_coef[3] = dA * L2E; g_coef[4] = dB * L2E; g_coef[5] = dT * L2E;
        g_coef[6] = qA; g_coef[7] = qB; g_coef[8] = qT;
        g_coef[9] = bm[0];
    }
    if (i >= NCROSS) return;
    g_cnt[i] = 0;

    int p = i / NC0, c = i % NC0;
    const int* g; const float* r; const int* cA; const int* cB; float pA, pB;
    if (p == 0)      { g = g01; r = r01; cA = c0; cB = c1; pA = 0.f; pB = 1.f; }
    else if (p == 1) { g = g12; r = r12; cA = c1; cB = c2; pA = 1.f; pB = 2.f; }
    else             { g = g20; r = r20; cA = c2; cB = c0; pA = 2.f; pB = 0.f; }
    int wA = g[2 * c], wB = g[2 * c + 1];
    int chA = cA[wA], chB = cB[wB];
    float rx = r[2 * c], ry = r[2 * c + 1];
    float fwA = (float)wA, fwB = (float)wB, fcA = (float)chA, fcB = (float)chB;
    float sb = 0.f, db = 0.f, qb = 0.f;
#pragma unroll
    for (int o = 0; o < 4; o++) {
        float base = bg[o]
              + fwA * W[4  + o] + fcA * W[8  + o] + pA * W[16 + o]
              + fwB * W[24 + o] + fcB * W[28 + o] + pB * W[36 + o]
              + rx  * W[40 + o] + ry  * W[44 + o];
        sb += base * asrc[o];
        db += base * adst[o];
        qb += base * Wm[o];
    }
    g_nb[i]    = make_float4(sb * L2E, db * L2E, qb, 0.f);
    g_chanA[i] = chA;
    g_chanB[i] = chB;
}

// ---------------- fused scatter + sdq (independent work, one launch) ----------------
// Blocks [0, SCATB): bucket scatter, 1 edge/thread (latency-bound atomics
// overlap with the streaming sdq blocks). Blocks [SCATB, SCATB+SDQB): s,q.
__global__ __launch_bounds__(256) void k_work(const int* __restrict__ edges,
                                              const float* __restrict__ x)
{
    int b = blockIdx.x;
    if (b < SCATB) {
        int e = b * 256 + threadIdx.x;
        if (e < NE) {
            int s = edges[e];
            int d = edges[NE + e];
            int p = atomicAdd(&g_cnt[d], 1);
            if (p < DEGCAP) g_csr[d * DEGCAP + p] = s * TT2;
        }
        return;
    }
    int idx = (b - SCATB) * 256 + threadIdx.x;   // [0, NCROSS*TT2)
    if (idx >= NCROSS * TT2) return;
    int n  = idx / TT2;
    int tp = idx % TT2;
    const float2* x2 = (const float2*)x;
    float2 xA = __ldg(&x2[g_chanA[n] * TT2 + tp]);
    float2 xB = __ldg(&x2[g_chanB[n] * TT2 + tp]);
    float4 nb = g_nb[n];
    float t0 = (float)(2 * tp), t1 = t0 + 1.f;
    float cSA = g_coef[0], cSB = g_coef[1], cST = g_coef[2];
    float cQA = g_coef[6], cQB = g_coef[7], cQT = g_coef[8];

    float s0 = nb.x + xA.x * cSA + xB.x * cSB + t0 * cST;
    float s1 = nb.x + xA.y * cSA + xB.y * cSB + t1 * cST;
    float q0 = nb.z + xA.x * cQA + xB.x * cQB + t0 * cQT;
    float q1 = nb.z + xA.y * cQA + xB.y * cQB + t1 * cQT;

    g_sq4[idx] = make_float4(s0, q0, s1, q1);
}

// ---------------- GAT aggregation (R7 online softmax, exp2 domain) ----------------
// Warp = node; lane owns ticks {2l, 2l+1, 64+2l, 65+2l}; 8 nodes/block.
// Inner loop shape identical to the measured-best R7 version; exp2 with
// prescaled s,d removes the hidden x*log2e FMULs of __expf.
__global__ __launch_bounds__(256) void k_agg(const float* __restrict__ x,
                                             float* __restrict__ out)
{
    __shared__ float s_res[TT * 9];
    int tid  = threadIdx.x;
    int warp = tid >> 5, lane = tid & 31;
    int n0 = blockIdx.x * 8;
    int n  = n0 + warp;
    int deg = g_cnt[n];
    if (deg > DEGCAP) deg = DEGCAP;
    const int* row = g_csr + n * DEGCAP;
    float bmlp = g_coef[9];
    float cDA = g_coef[3], cDB = g_coef[4], cDT = g_coef[5];

    // dv for this lane's 4 ticks (scaled domain)
    const float2* x2 = (const float2*)x;
    float4 nb = g_nb[n];
    int chA = g_chanA[n], chB = g_chanB[n];
    float dv[4], m[4], den[4], acc[4];
#pragma unroll
    for (int k = 0; k < 2; k++) {
        float2 xA = x2[chA * TT2 + lane + 32 * k];
        float2 xB = x2[chB * TT2 + lane + 32 * k];
        float t0 = (float)(2 * (lane + 32 * k));
        dv[2 * k]     = nb.y + xA.x * cDA + xB.x * cDB + t0 * cDT;
        dv[2 * k + 1] = nb.y + xA.y * cDA + xB.y * cDB + (t0 + 1.f) * cDT;
    }
#pragma unroll
    for (int k = 0; k < 4; k++) { m[k] = -1e30f; den[k] = 0.f; acc[k] = 0.f; }

    int rv_next = (deg > 0) ? row[0] : 0;
    for (int j = 0; j < deg; j++) {
        int rv = rv_next;
        if (j + 1 < deg) rv_next = row[j + 1];
        float4 sq0 = g_sq4[rv + lane];        // ticks 2l, 2l+1
        float4 sq1 = g_sq4[rv + 32 + lane];   // ticks 64+2l, 65+2l
        float es[4] = { sq0.x, sq0.z, sq1.x, sq1.z };
        float qs[4] = { sq0.y, sq0.w, sq1.y, sq1.w };
#pragma unroll
        for (int k = 0; k < 4; k++) {
            float e = es[k] + dv[k];
            e = fmaxf(e, 0.2f * e);                 // leaky (scaled domain)
            float nm = fmaxf(m[k], e);
            float r = exp2f(m[k] - nm);             // independent MUFUs (R7 shape)
            float w = exp2f(e - nm);
            den[k] = fmaf(den[k], r, w);
            acc[k] = fmaf(acc[k], r, w * qs[k]);
            m[k] = nm;
        }
    }
    // ticks for k: 0->2l, 1->2l+1, 2->64+2l, 3->65+2l
#pragma unroll
    for (int k = 0; k < 4; k++) {
        int t = 2 * lane + (k & 1) + 64 * (k >> 1);
        float z = acc[k] / (den[k] + 1e-9f) + bmlp;
        s_res[t * 9 + warp] = 1.f / (1.f + __expf(-z));
    }
    __syncthreads();
#pragma unroll
    for (int p = 0; p < 4; p++) {
        int i = p * 256 + tid;
        int t = i >> 3, c = i & 7;
        out[t * NCROSS + n0 + c] = s_res[t * 9 + c];
    }
}

// ---------------- launch ----------------
extern "C" void kernel_launch(void* const* d_in, const int* in_sizes, int n_in,
                              void* d_out, int out_size)
{
    const float* x    = (const float*)d_in[0];
    const int*   c0   = (const int*)  d_in[1];
    const int*   c1   = (const int*)  d_in[2];
    const int*   c2   = (const int*)  d_in[3];
    const int*   g01  = (const int*)  d_in[4];
    const int*   g12  = (const int*)  d_in[5];
    const int*   g20  = (const int*)  d_in[6];
    const float* r01  = (const float*)d_in[7];
    const float* r12  = (const float*)d_in[8];
    const float* r20  = (const float*)d_in[9];
    const int*   edges= (const int*)  d_in[10];
    const float* Wg   = (const float*)d_in[11];
    const float* asrc = (const float*)d_in[12];
    const float* adst = (const float*)d_in[13];
    const float* bg   = (const float*)d_in[14];
    const float* Wm   = (const float*)d_in[15];
    const float* bm   = (const float*)d_in[16];
    float* out = (float*)d_out;

    const int B = 256;
    k_init<<<(NCROSS + B - 1) / B, B>>>(c0, c1, c2, g01, g12, g20,
                                        r01, r12, r20, Wg, bg, asrc, adst, Wm, bm);
    k_work<<<SCATB + SDQB, B>>>(edges, x);
    k_agg<<<NCROSS / 8, B>>>(x, out);
}